// round 2
// baseline (speedup 1.0000x reference)
#include <cuda_runtime.h>
#include <cstdint>

// ----------------------------------------------------------------------------
// second_roi: N=512, C=512, H=W=14, CH=CW=7.
// Whole pipeline is linear in `project`; conv1x1 commutes with RoIAlign.
//   out[n,o] = const[o] + sum_{c0,q} D[o,c0,q] * project[n,c0,q]
// Precompute D (10 x 512 x 196) from weights, then one DRAM-bound pass.
// ----------------------------------------------------------------------------

#define NQ   196          // 14*14
#define KTOT 100352       // 512*196
#define CHUNKS 28
#define KCH   3584        // KTOT / CHUNKS, multiple of 128

__device__ float g_W21 [512 * 512];
__device__ float g_Amat[490 * 512];
__device__ float g_D0  [490 * 512];
__device__ float g_const[10];
__device__ float g_Dp  [KTOT * 12];            // padded rows of 12 floats (48B, 16B-aligned)
__device__ float g_part[CHUNKS * 512 * 10];    // per-k-chunk partial outputs

// ---------------- packed f32x2 helpers ----------------
__device__ __forceinline__ unsigned long long pk2(float lo, float hi) {
    unsigned long long r;
    asm("mov.b64 %0, {%1,%2};" : "=l"(r) : "f"(lo), "f"(hi));
    return r;
}
__device__ __forceinline__ void upk2(unsigned long long v, float& lo, float& hi) {
    asm("mov.b64 {%0,%1}, %2;" : "=f"(lo), "=f"(hi) : "l"(v));
}
__device__ __forceinline__ unsigned long long fma2(unsigned long long a,
                                                   unsigned long long b,
                                                   unsigned long long c) {
    unsigned long long d;
    asm("fma.rn.f32x2 %0, %1, %2, %3;" : "=l"(d) : "l"(a), "l"(b), "l"(c));
    return d;
}
__device__ __forceinline__ unsigned long long add2(unsigned long long a,
                                                   unsigned long long b) {
    unsigned long long d;
    asm("add.rn.f32x2 %0, %1, %2;" : "=l"(d) : "l"(a), "l"(b));
    return d;
}

// ---------------- generic 64x64 tiled SGEMM (3 jobs) ----------------
// job 0: W21  = w2 @ w1                     (512 x 512, K=512)
// job 1: Amat[(o,p),c2] = sum_c wn[o,c,p] * w3[c,c2]   (490 x 512, K=512)
// job 2: D0   = Amat @ W21                  (490 x 512, K=512)
__global__ __launch_bounds__(256) void gemm_kernel(
    const float* __restrict__ w1, const float* __restrict__ w2,
    const float* __restrict__ w3,
    const float* __restrict__ wnote, const float* __restrict__ wreg,
    int job_base)
{
    const int job = job_base + blockIdx.z;
    __shared__ float As[16][68];
    __shared__ float Bs[16][68];

    const float* A = nullptr;
    const float* B;
    float* C;
    int M;
    if (job == 0)      { A = w2;      B = w1;    C = g_W21;  M = 512; }
    else if (job == 1) {              B = w3;    C = g_Amat; M = 490; }
    else               { A = g_Amat;  B = g_W21; C = g_D0;   M = 490; }

    const int m0 = blockIdx.y * 64, n0 = blockIdx.x * 64;
    const int tid = threadIdx.x;
    const int tx = tid & 15, ty = tid >> 4;

    unsigned long long acc[4][2];
#pragma unroll
    for (int i = 0; i < 4; i++) { acc[i][0] = 0ull; acc[i][1] = 0ull; }

    const int lm  = m0 + (tid >> 2);   // A-tile row this thread loads
    const int lk4 = (tid & 3) * 4;     // A-tile k offset
    const int br  = tid >> 4;          // B-tile row
    const int bc4 = (tid & 15) * 4;    // B-tile col

    const float* wnbase = nullptr;
    if (job == 1 && lm < 490) {
        int o = lm / 49, p = lm % 49;
        wnbase = (o < 2 ? wnote + (size_t)o * 25088
                        : wreg  + (size_t)(o - 2) * 25088) + p;
    }

    for (int k0 = 0; k0 < 512; k0 += 16) {
        float va[4];
        if (job == 1) {
            if (wnbase) {
#pragma unroll
                for (int j = 0; j < 4; j++) va[j] = wnbase[(size_t)(k0 + lk4 + j) * 49];
            } else {
#pragma unroll
                for (int j = 0; j < 4; j++) va[j] = 0.0f;
            }
        } else {
            if (lm < M) {
                float4 t = *(const float4*)&A[(size_t)lm * 512 + k0 + lk4];
                va[0] = t.x; va[1] = t.y; va[2] = t.z; va[3] = t.w;
            } else {
#pragma unroll
                for (int j = 0; j < 4; j++) va[j] = 0.0f;
            }
        }
        float4 bv = *(const float4*)&B[(size_t)(k0 + br) * 512 + n0 + bc4];

        __syncthreads();
#pragma unroll
        for (int j = 0; j < 4; j++) As[lk4 + j][tid >> 2] = va[j];
        *(float4*)&Bs[br][bc4] = bv;
        __syncthreads();

#pragma unroll
        for (int k = 0; k < 16; k++) {
            float4 a = *(const float4*)&As[k][ty * 4];
            float4 b = *(const float4*)&Bs[k][tx * 4];
            unsigned long long b01 = pk2(b.x, b.y), b23 = pk2(b.z, b.w);
            float af[4] = {a.x, a.y, a.z, a.w};
#pragma unroll
            for (int i = 0; i < 4; i++) {
                unsigned long long ai = pk2(af[i], af[i]);
                acc[i][0] = fma2(ai, b01, acc[i][0]);
                acc[i][1] = fma2(ai, b23, acc[i][1]);
            }
        }
    }

#pragma unroll
    for (int i = 0; i < 4; i++) {
        int m = m0 + ty * 4 + i;
        if (m < M) {
            float4 o;
            upk2(acc[i][0], o.x, o.y);
            upk2(acc[i][1], o.z, o.w);
            *(float4*)&C[(size_t)m * 512 + n0 + tx * 4] = o;
        }
    }
}

// ---------------- bias constants ----------------
// b2eff = w2@b1 + b2 ; const[o] = bhead[o] + sum_{c,p} wn[o,c,p]*b3[c]
//                                + sum_{p,c2} Amat[(o,p),c2]*b2eff[c2]
__global__ void bias_kernel(
    const float* __restrict__ w2, const float* __restrict__ b1,
    const float* __restrict__ b2, const float* __restrict__ b3,
    const float* __restrict__ wnote, const float* __restrict__ wreg,
    const float* __restrict__ bnote, const float* __restrict__ breg)
{
    __shared__ float sb2[512];
    const int tid = threadIdx.x;          // 512 threads, 16 warps
    const int w = tid >> 5, lane = tid & 31;

    for (int r = 0; r < 32; r++) {
        int c2 = w * 32 + r;
        float acc = 0.0f;
        for (int c1 = lane; c1 < 512; c1 += 32)
            acc += w2[(size_t)c2 * 512 + c1] * b1[c1];
#pragma unroll
        for (int off = 16; off; off >>= 1)
            acc += __shfl_xor_sync(0xffffffffu, acc, off);
        if (lane == 0) sb2[c2] = acc + b2[c2];
    }
    __syncthreads();

    if (w < 10) {
        const float* wn = (w < 2) ? wnote + (size_t)w * 25088
                                  : wreg  + (size_t)(w - 2) * 25088;
        float acc = 0.0f;
        for (int c = lane; c < 512; c += 32) {
            float bc = b3[c];
            const float* rp = wn + (size_t)c * 49;
#pragma unroll
            for (int p = 0; p < 49; p++) acc += rp[p] * bc;
        }
        for (int p = 0; p < 49; p++) {
            const float* ap = g_Amat + (size_t)(w * 49 + p) * 512;
            for (int c2 = lane; c2 < 512; c2 += 32) acc += ap[c2] * sb2[c2];
        }
#pragma unroll
        for (int off = 16; off; off >>= 1)
            acc += __shfl_xor_sync(0xffffffffu, acc, off);
        if (lane == 0)
            g_const[w] = ((w < 2) ? bnote[w] : breg[w - 2]) + acc;
    }
}

// ---------------- fold bilinear R into D0 -> Dp ----------------
// Dp[k=(c0*196+q)][o] = sum_{py,px} wy(py,qy)*wx(px,qx) * D0[(o*49+py*7+px), c0]
__global__ void fold_kernel()
{
    const int idx = blockIdx.x * 256 + threadIdx.x;  // KTOT*12 total
    if (idx >= KTOT * 12) return;
    const int j = idx % 12;
    const int k = idx / 12;
    if (j >= 10) { g_Dp[idx] = 0.0f; return; }

    const int c0 = k / NQ;
    const int q  = k % NQ;
    const int qy = q / 14, qx = q % 14;

    // sampling grid (mirrors reference fp32 math; box = [0,0,13,13])
    const float sh   = 13.0f / 7.0f;
    const float ny0  = (sh * 0.5f - 0.5f) / 13.0f;
    const float nh   = sh * 6.0f / 13.0f;
    const float step = (nh * 13.0f) / 6.0f;
    const float base = ny0 * 13.0f;

    float s = 0.0f;
#pragma unroll
    for (int py = 0; py < 7; py++) {
        float yv  = base + (float)py * step;
        float y0f = floorf(yv);
        float fy  = yv - y0f;
        int   y0  = (int)y0f;
        int   y0c = max(0, min(y0, 13));
        int   y1c = min(y0c + 1, 13);
        float wy  = (qy == y0c) ? (1.0f - fy) : ((qy == y1c) ? fy : 0.0f);
        if (wy == 0.0f) continue;
#pragma unroll
        for (int px = 0; px < 7; px++) {
            float xv  = base + (float)px * step;
            float x0f = floorf(xv);
            float fx  = xv - x0f;
            int   x0  = (int)x0f;
            int   x0c = max(0, min(x0, 13));
            int   x1c = min(x0c + 1, 13);
            float wx  = (qx == x0c) ? (1.0f - fx) : ((qx == x1c) ? fx : 0.0f);
            if (wx != 0.0f)
                s += wy * wx * g_D0[(size_t)(j * 49 + py * 7 + px) * 512 + c0];
        }
    }
    g_Dp[idx] = s;
}

// ---------------- main streaming pass ----------------
// grid (CHUNKS=28, 16); block 256 = 8 warps; each warp: 4 consecutive n,
// lanes cover 128 consecutive k per iter (float4 per lane). D chunk (172KB)
// is shared across the block's 8 warps through L1.
__global__ __launch_bounds__(256) void main_kernel(const float* __restrict__ proj)
{
    const int warp = threadIdx.x >> 5, lane = threadIdx.x & 31;
    const int n0 = (blockIdx.y * 8 + warp) * 4;
    const size_t kbase = (size_t)blockIdx.x * KCH;
    const float* p0 = proj + (size_t)n0 * KTOT + kbase;

    unsigned long long acc[4][5];
#pragma unroll
    for (int i = 0; i < 4; i++)
#pragma unroll
        for (int s = 0; s < 5; s++) acc[i][s] = 0ull;

    for (int it = 0; it < KCH / 128; it++) {
        const size_t koff = (size_t)it * 128 + lane * 4;
        float4 pv0 = *(const float4*)(p0 + koff);
        float4 pv1 = *(const float4*)(p0 + (size_t)1 * KTOT + koff);
        float4 pv2 = *(const float4*)(p0 + (size_t)2 * KTOT + koff);
        float4 pv3 = *(const float4*)(p0 + (size_t)3 * KTOT + koff);
        float pf[4][4] = {{pv0.x, pv0.y, pv0.z, pv0.w},
                          {pv1.x, pv1.y, pv1.z, pv1.w},
                          {pv2.x, pv2.y, pv2.z, pv2.w},
                          {pv3.x, pv3.y, pv3.z, pv3.w}};
        const ulonglong2* dbase = (const ulonglong2*)(g_Dp + (kbase + koff) * 12);
#pragma unroll
        for (int j = 0; j < 4; j++) {
            ulonglong2 dA = dbase[j * 3 + 0];
            ulonglong2 dB = dbase[j * 3 + 1];
            ulonglong2 dC = dbase[j * 3 + 2];
            unsigned long long d[5] = {dA.x, dA.y, dB.x, dB.y, dC.x};
#pragma unroll
            for (int i = 0; i < 4; i++) {
                unsigned long long pp = pk2(pf[i][j], pf[i][j]);
#pragma unroll
                for (int s = 0; s < 5; s++) acc[i][s] = fma2(pp, d[s], acc[i][s]);
            }
        }
    }

    // warp butterfly reduce (packed)
#pragma unroll
    for (int i = 0; i < 4; i++)
#pragma unroll
        for (int s = 0; s < 5; s++) {
            unsigned long long v = acc[i][s];
#pragma unroll
            for (int off = 16; off; off >>= 1)
                v = add2(v, __shfl_xor_sync(0xffffffffu, v, off));
            acc[i][s] = v;
        }

    if (lane == 0) {
#pragma unroll
        for (int i = 0; i < 4; i++) {
            float* dst = g_part + ((size_t)blockIdx.x * 512 + (n0 + i)) * 10;
#pragma unroll
            for (int s = 0; s < 5; s++) {
                float lo, hi;
                upk2(acc[i][s], lo, hi);
                dst[2 * s]     = lo;
                dst[2 * s + 1] = hi;
            }
        }
    }
}

// ---------------- final reduce over k-chunks + bias ----------------
__global__ void final_kernel(float* __restrict__ out)
{
    const int i = blockIdx.x * 256 + threadIdx.x;  // 5120 outputs
    if (i >= 5120) return;
    int n, o;
    if (i < 1024) { n = i >> 1; o = i & 1; }
    else          { int j = i - 1024; n = j >> 3; o = 2 + (j & 7); }
    float s = g_const[o];
#pragma unroll
    for (int c = 0; c < CHUNKS; c++)
        s += g_part[((size_t)c * 512 + n) * 10 + o];
    out[i] = s;
}

// ---------------- launch ----------------
extern "C" void kernel_launch(void* const* d_in, const int* in_sizes, int n_in,
                              void* d_out, int out_size)
{
    const float* project = (const float*)d_in[0];
    const float* w1    = (const float*)d_in[1];
    const float* b1    = (const float*)d_in[2];
    const float* w2    = (const float*)d_in[3];
    const float* b2    = (const float*)d_in[4];
    const float* w3    = (const float*)d_in[5];
    const float* b3    = (const float*)d_in[6];
    const float* wnote = (const float*)d_in[7];
    const float* bnote = (const float*)d_in[8];
    const float* wreg  = (const float*)d_in[9];
    const float* breg  = (const float*)d_in[10];
    float* out = (float*)d_out;

    // W21 = w2@w1 and Amat = wn (x)_c w3 : independent, one launch
    gemm_kernel<<<dim3(8, 8, 2), 256>>>(w1, w2, w3, wnote, wreg, 0);
    // bias constants (needs Amat)
    bias_kernel<<<1, 512>>>(w2, b1, b2, b3, wnote, wreg, bnote, breg);
    // D0 = Amat @ W21
    gemm_kernel<<<dim3(8, 8, 1), 256>>>(w1, w2, w3, wnote, wreg, 2);
    // fold bilinear R, build padded AoS Dp
    fold_kernel<<<(KTOT * 12) / 256, 256>>>();
    // DRAM-bound streaming contraction
    main_kernel<<<dim3(CHUNKS, 16), 256>>>(project);
    // reduce partials + bias
    final_kernel<<<20, 256>>>(out);
}

// round 5
// speedup vs baseline: 1.2843x; 1.2843x over previous
#include <cuda_runtime.h>
#include <cstdint>

// ----------------------------------------------------------------------------
// second_roi: N=512, C=512, H=W=14, CH=CW=7.
// Whole pipeline is linear in `project`; conv1x1 commutes with RoIAlign.
//   out[n,o] = const[o] + sum_{c0,q} D[o,c0,q] * project[n,c0,q]
// Precompute D (10 x 512 x 196) from weights, then one DRAM-bound pass.
// R2: SoA o-pair planes for coalesced D loads; scalar-FFMA gemm; smem fold.
// ----------------------------------------------------------------------------

#define NQ   196          // 14*14
#define KTOT 100352       // 512*196
#define CHUNKS 28
#define KCH   3584        // KTOT / CHUNKS, multiple of 64

__device__ float g_W21 [512 * 512];
__device__ float g_Amat[490 * 512];
__device__ float g_D0T [512 * 512];            // transposed: [c0][o*49+p]
__device__ float g_const[10];
__device__ unsigned long long g_Dq[5 * KTOT];  // o-pair planes: g_Dq[s*KTOT + k]
__device__ float g_part[CHUNKS * 512 * 10];    // per-k-chunk partial outputs

// ---------------- packed f32x2 helpers ----------------
__device__ __forceinline__ unsigned long long pk2(float lo, float hi) {
    unsigned long long r;
    asm("mov.b64 %0, {%1,%2};" : "=l"(r) : "f"(lo), "f"(hi));
    return r;
}
__device__ __forceinline__ void upk2(unsigned long long v, float& lo, float& hi) {
    asm("mov.b64 {%0,%1}, %2;" : "=f"(lo), "=f"(hi) : "l"(v));
}
__device__ __forceinline__ unsigned long long fma2(unsigned long long a,
                                                   unsigned long long b,
                                                   unsigned long long c) {
    unsigned long long d;
    asm("fma.rn.f32x2 %0, %1, %2, %3;" : "=l"(d) : "l"(a), "l"(b), "l"(c));
    return d;
}
__device__ __forceinline__ unsigned long long add2(unsigned long long a,
                                                   unsigned long long b) {
    unsigned long long d;
    asm("add.rn.f32x2 %0, %1, %2;" : "=l"(d) : "l"(a), "l"(b));
    return d;
}

// ---------------- generic 64x64 tiled SGEMM (3 jobs, scalar FFMA) ----------------
// job 0: W21  = w2 @ w1                               (512 x 512, K=512)
// job 1: Amat[(o,p),c2] = sum_c wn[o,c,p] * w3[c,c2]  (490 x 512, K=512)
// job 2: D0T[c2][m] = (Amat @ W21)^T                  (490 x 512, K=512, transposed store)
__global__ __launch_bounds__(256) void gemm_kernel(
    const float* __restrict__ w1, const float* __restrict__ w2,
    const float* __restrict__ w3,
    const float* __restrict__ wnote, const float* __restrict__ wreg,
    int job_base)
{
    const int job = job_base + blockIdx.z;
    __shared__ float As[16][68];
    __shared__ float Bs[16][68];

    const float* A = nullptr;
    const float* B;
    int M;
    if (job == 0)      { A = w2;      B = w1;    M = 512; }
    else if (job == 1) {              B = w3;    M = 490; }
    else               { A = g_Amat;  B = g_W21; M = 490; }

    const int m0 = blockIdx.y * 64, n0 = blockIdx.x * 64;
    const int tid = threadIdx.x;
    const int tx = tid & 15, ty = tid >> 4;

    float acc[4][4];
#pragma unroll
    for (int i = 0; i < 4; i++)
#pragma unroll
        for (int j = 0; j < 4; j++) acc[i][j] = 0.0f;

    const int lm  = m0 + (tid >> 2);   // A-tile row this thread loads
    const int lk4 = (tid & 3) * 4;     // A-tile k offset
    const int br  = tid >> 4;          // B-tile row
    const int bc4 = (tid & 15) * 4;    // B-tile col

    const float* wnbase = nullptr;
    if (job == 1 && lm < 490) {
        int o = lm / 49, p = lm % 49;
        wnbase = (o < 2 ? wnote + (size_t)o * 25088
                        : wreg  + (size_t)(o - 2) * 25088) + p;
    }

    for (int k0 = 0; k0 < 512; k0 += 16) {
        float va[4];
        if (job == 1) {
            if (wnbase) {
#pragma unroll
                for (int j = 0; j < 4; j++) va[j] = wnbase[(size_t)(k0 + lk4 + j) * 49];
            } else {
#pragma unroll
                for (int j = 0; j < 4; j++) va[j] = 0.0f;
            }
        } else {
            if (lm < M) {
                float4 t = *(const float4*)&A[(size_t)lm * 512 + k0 + lk4];
                va[0] = t.x; va[1] = t.y; va[2] = t.z; va[3] = t.w;
            } else {
#pragma unroll
                for (int j = 0; j < 4; j++) va[j] = 0.0f;
            }
        }
        float4 bv = *(const float4*)&B[(size_t)(k0 + br) * 512 + n0 + bc4];

        __syncthreads();
#pragma unroll
        for (int j = 0; j < 4; j++) As[lk4 + j][tid >> 2] = va[j];
        *(float4*)&Bs[br][bc4] = bv;
        __syncthreads();

#pragma unroll
        for (int k = 0; k < 16; k++) {
            float4 a = *(const float4*)&As[k][ty * 4];
            float4 b = *(const float4*)&Bs[k][tx * 4];
            float af[4] = {a.x, a.y, a.z, a.w};
            float bf[4] = {b.x, b.y, b.z, b.w};
#pragma unroll
            for (int i = 0; i < 4; i++)
#pragma unroll
                for (int j = 0; j < 4; j++)
                    acc[i][j] = fmaf(af[i], bf[j], acc[i][j]);
        }
    }

    if (job == 2) {
        // transposed store: D0T[c2][m]
#pragma unroll
        for (int i = 0; i < 4; i++) {
            int m = m0 + ty * 4 + i;
            if (m < M) {
#pragma unroll
                for (int j = 0; j < 4; j++)
                    g_D0T[(size_t)(n0 + tx * 4 + j) * 512 + m] = acc[i][j];
            }
        }
    } else {
        float* C = (job == 0) ? g_W21 : g_Amat;
#pragma unroll
        for (int i = 0; i < 4; i++) {
            int m = m0 + ty * 4 + i;
            if (m < M)
                *(float4*)&C[(size_t)m * 512 + n0 + tx * 4] =
                    make_float4(acc[i][0], acc[i][1], acc[i][2], acc[i][3]);
        }
    }
}

// ---------------- bias constants ----------------
// b2eff = w2@b1 + b2 ; const[o] = bhead[o] + sum_{c,p} wn[o,c,p]*b3[c]
//                                + sum_{p,c2} Amat[(o,p),c2]*b2eff[c2]
__global__ void bias_kernel(
    const float* __restrict__ w2, const float* __restrict__ b1,
    const float* __restrict__ b2, const float* __restrict__ b3,
    const float* __restrict__ wnote, const float* __restrict__ wreg,
    const float* __restrict__ bnote, const float* __restrict__ breg)
{
    __shared__ float sb2[512];
    const int tid = threadIdx.x;          // 512 threads, 16 warps
    const int w = tid >> 5, lane = tid & 31;

    for (int r = 0; r < 32; r++) {
        int c2 = w * 32 + r;
        float acc = 0.0f;
        for (int c1 = lane; c1 < 512; c1 += 32)
            acc += w2[(size_t)c2 * 512 + c1] * b1[c1];
#pragma unroll
        for (int off = 16; off; off >>= 1)
            acc += __shfl_xor_sync(0xffffffffu, acc, off);
        if (lane == 0) sb2[c2] = acc + b2[c2];
    }
    __syncthreads();

    if (w < 10) {
        const float* wn = (w < 2) ? wnote + (size_t)w * 25088
                                  : wreg  + (size_t)(w - 2) * 25088;
        float acc = 0.0f;
        for (int c = lane; c < 512; c += 32) {
            float bc = b3[c];
            const float* rp = wn + (size_t)c * 49;
#pragma unroll
            for (int p = 0; p < 49; p++) acc += rp[p] * bc;
        }
        for (int p = 0; p < 49; p++) {
            const float* ap = g_Amat + (size_t)(w * 49 + p) * 512;
            for (int c2 = lane; c2 < 512; c2 += 32) acc += ap[c2] * sb2[c2];
        }
#pragma unroll
        for (int off = 16; off; off >>= 1)
            acc += __shfl_xor_sync(0xffffffffu, acc, off);
        if (lane == 0)
            g_const[w] = ((w < 2) ? bnote[w] : breg[w - 2]) + acc;
    }
}

// ---------------- fold bilinear R: D0T -> SoA o-pair planes g_Dq ----------------
// g_Dq[s][c0*196+q] = pack( val(o=2s), val(o=2s+1) )
// val(o) = sum_{py,px} wy(py,qy)*wx(px,qx) * D0T[c0][o*49+py*7+px]
__global__ __launch_bounds__(256) void fold_kernel()
{
    __shared__ float srow[490];
    const int c0 = blockIdx.x;
    for (int i = threadIdx.x; i < 490; i += 256)
        srow[i] = g_D0T[(size_t)c0 * 512 + i];
    __syncthreads();

    // sampling grid (mirrors reference fp32 math; box = [0,0,13,13])
    const float sh   = 13.0f / 7.0f;
    const float ny0  = (sh * 0.5f - 0.5f) / 13.0f;
    const float nh   = sh * 6.0f / 13.0f;
    const float step = (nh * 13.0f) / 6.0f;
    const float base = ny0 * 13.0f;

    for (int t = threadIdx.x; t < 980; t += 256) {
        const int s = t / 196;        // o-pair plane
        const int q = t % 196;
        const int qy = q / 14, qx = q % 14;
        const int o0 = 2 * s;

        float v0 = 0.0f, v1 = 0.0f;
#pragma unroll
        for (int py = 0; py < 7; py++) {
            float yv  = base + (float)py * step;
            float y0f = floorf(yv);
            float fy  = yv - y0f;
            int   y0c = max(0, min((int)y0f, 13));
            int   y1c = min(y0c + 1, 13);
            float wy  = (qy == y0c) ? (1.0f - fy) : ((qy == y1c) ? fy : 0.0f);
            if (wy == 0.0f) continue;
#pragma unroll
            for (int px = 0; px < 7; px++) {
                float xv  = base + (float)px * step;
                float x0f = floorf(xv);
                float fx  = xv - x0f;
                int   x0c = max(0, min((int)x0f, 13));
                int   x1c = min(x0c + 1, 13);
                float wx  = (qx == x0c) ? (1.0f - fx) : ((qx == x1c) ? fx : 0.0f);
                if (wx != 0.0f) {
                    float wgt = wy * wx;
                    int   p   = py * 7 + px;
                    v0 = fmaf(wgt, srow[o0 * 49 + p], v0);
                    v1 = fmaf(wgt, srow[(o0 + 1) * 49 + p], v1);
                }
            }
        }
        g_Dq[(size_t)s * KTOT + (size_t)c0 * 196 + q] = pk2(v0, v1);
    }
}

// ---------------- main streaming pass ----------------
// grid (CHUNKS=28, 16); block 256 = 8 warps; each warp: 4 consecutive n,
// lanes cover 64 consecutive k per iter (float2 proj, ulonglong2 D per plane).
// All loads fully coalesced; D planes are L2-resident (4MB).
__global__ __launch_bounds__(256) void main_kernel(const float* __restrict__ proj)
{
    const int warp = threadIdx.x >> 5, lane = threadIdx.x & 31;
    const int n0 = (blockIdx.y * 8 + warp) * 4;
    const size_t kbase = (size_t)blockIdx.x * KCH;
    const float* p0 = proj + (size_t)n0 * KTOT + kbase;

    unsigned long long acc[4][5];
#pragma unroll
    for (int i = 0; i < 4; i++)
#pragma unroll
        for (int s = 0; s < 5; s++) acc[i][s] = 0ull;

#pragma unroll 2
    for (int it = 0; it < KCH / 64; it++) {
        const size_t koff = (size_t)it * 64 + lane * 2;

        float2 pv[4];
#pragma unroll
        for (int i = 0; i < 4; i++)
            pv[i] = *(const float2*)(p0 + (size_t)i * KTOT + koff);

        ulonglong2 dv[5];
#pragma unroll
        for (int s = 0; s < 5; s++)
            dv[s] = *(const ulonglong2*)(g_Dq + (size_t)s * KTOT + kbase + koff);

#pragma unroll
        for (int i = 0; i < 4; i++) {
            unsigned long long pa = pk2(pv[i].x, pv[i].x);
            unsigned long long pb = pk2(pv[i].y, pv[i].y);
#pragma unroll
            for (int s = 0; s < 5; s++) {
                acc[i][s] = fma2(pa, dv[s].x, acc[i][s]);
                acc[i][s] = fma2(pb, dv[s].y, acc[i][s]);
            }
        }
    }

    // warp butterfly reduce (packed)
#pragma unroll
    for (int i = 0; i < 4; i++)
#pragma unroll
        for (int s = 0; s < 5; s++) {
            unsigned long long v = acc[i][s];
#pragma unroll
            for (int off = 16; off; off >>= 1)
                v = add2(v, __shfl_xor_sync(0xffffffffu, v, off));
            acc[i][s] = v;
        }

    if (lane == 0) {
#pragma unroll
        for (int i = 0; i < 4; i++) {
            float* dst = g_part + ((size_t)blockIdx.x * 512 + (n0 + i)) * 10;
#pragma unroll
            for (int s = 0; s < 5; s++) {
                float lo, hi;
                upk2(acc[i][s], lo, hi);
                dst[2 * s]     = lo;
                dst[2 * s + 1] = hi;
            }
        }
    }
}

// ---------------- final reduce over k-chunks + bias ----------------
__global__ void final_kernel(float* __restrict__ out)
{
    const int i = blockIdx.x * 256 + threadIdx.x;  // 5120 outputs
    if (i >= 5120) return;
    int n, o;
    if (i < 1024) { n = i >> 1; o = i & 1; }
    else          { int j = i - 1024; n = j >> 3; o = 2 + (j & 7); }
    float s = g_const[o];
#pragma unroll
    for (int c = 0; c < CHUNKS; c++)
        s += g_part[((size_t)c * 512 + n) * 10 + o];
    out[i] = s;
}

// ---------------- launch ----------------
extern "C" void kernel_launch(void* const* d_in, const int* in_sizes, int n_in,
                              void* d_out, int out_size)
{
    const float* project = (const float*)d_in[0];
    const float* w1    = (const float*)d_in[1];
    const float* b1    = (const float*)d_in[2];
    const float* w2    = (const float*)d_in[3];
    const float* b2    = (const float*)d_in[4];
    const float* w3    = (const float*)d_in[5];
    const float* b3    = (const float*)d_in[6];
    const float* wnote = (const float*)d_in[7];
    const float* bnote = (const float*)d_in[8];
    const float* wreg  = (const float*)d_in[9];
    const float* breg  = (const float*)d_in[10];
    float* out = (float*)d_out;

    // W21 = w2@w1 and Amat = wn (x)_c w3 : independent, one launch (128 blocks)
    gemm_kernel<<<dim3(8, 8, 2), 256>>>(w1, w2, w3, wnote, wreg, 0);
    // D0T = (Amat @ W21)^T
    gemm_kernel<<<dim3(8, 8, 1), 256>>>(w1, w2, w3, wnote, wreg, 2);
    // bias constants (needs Amat)
    bias_kernel<<<1, 512>>>(w2, b1, b2, b3, wnote, wreg, bnote, breg);
    // fold bilinear R into SoA o-pair planes
    fold_kernel<<<512, 256>>>();
    // DRAM-bound streaming contraction
    main_kernel<<<dim3(CHUNKS, 16), 256>>>(project);
    // reduce partials + bias
    final_kernel<<<20, 256>>>(out);
}

// round 7
// speedup vs baseline: 1.9725x; 1.5358x over previous
#include <cuda_runtime.h>
#include <cstdint>

// ----------------------------------------------------------------------------
// second_roi: N=512, C=512, H=W=14, CH=CW=7.
// Pipeline is linear in `project`; conv1x1 commutes with RoIAlign.
//   out[n,o] = const[o] + sum_{c0,q} D[o,c0,q] * project[n,c0,q]
// R3: NO fma.rn.f32x2 anywhere (suspected slow pipe on sm_103a).
//     main: scalar FFMA + smem-staged D subtiles. gemm: double-buffered smem,
//     job2 retiled 32x64. fold: compact bilinear footprint lists.
// ----------------------------------------------------------------------------

#define NQ   196          // 14*14
#define KTOT 100352       // 512*196
#define CHUNKS 28
#define KCH   3584        // KTOT / CHUNKS
#define KS    896         // smem D subtile (KCH/4), multiple of 128

__device__ float g_W21 [512 * 512];
__device__ float g_Amat[490 * 512];
__device__ float g_D0T [512 * 512];          // transposed: [c0][o*49+p]
__device__ float g_b2eff[512];
__device__ float g_const[10];
__device__ float g_Df  [10 * KTOT];          // 10 scalar planes: g_Df[o*KTOT + k]
__device__ float g_part[CHUNKS * 512 * 10];  // per-k-chunk partial outputs

// ---------------- double-buffered tiled SGEMM, TM x 64 tiles ----------------
// job 0: W21  = w2 @ w1                               (512 x 512, K=512)
// job 1: Amat[(o,p),c2] = sum_c wn[o,c,p] * w3[c,c2]  (490 x 512, K=512)
// job 2: D0T[c2][m] = (Amat @ W21)^T                  (490 x 512, K=512)
template <int TM>
__global__ __launch_bounds__(256) void gemm_kernel(
    const float* __restrict__ w1, const float* __restrict__ w2,
    const float* __restrict__ w3,
    const float* __restrict__ wnote, const float* __restrict__ wreg,
    int job_base)
{
    const int job = job_base + blockIdx.z;
    __shared__ float As[2][16][TM + 4];
    __shared__ float Bs[2][16][68];

    const float* A = nullptr;
    const float* B;
    int M;
    if (job == 0)      { A = w2;      B = w1;    M = 512; }
    else if (job == 1) {              B = w3;    M = 490; }
    else               { A = g_Amat;  B = g_W21; M = 490; }

    const int m0 = blockIdx.y * TM, n0 = blockIdx.x * 64;
    const int tid = threadIdx.x;
    const int tx = tid & 15, ty = tid >> 4;
    constexpr int RM = TM / 16;            // rows per thread (4 or 2)

    float acc[RM][4];
#pragma unroll
    for (int i = 0; i < RM; i++)
#pragma unroll
        for (int j = 0; j < 4; j++) acc[i][j] = 0.0f;

    // A loaders: TM rows x 16 k -> TM*4 float4 loads, one per thread (first TM*4 threads)
    const bool aAct = (tid < TM * 4);
    const int lmr = tid >> 2;              // local row
    const int lm  = m0 + lmr;
    const int lk4 = (tid & 3) * 4;
    // B loaders: all 256 threads
    const int br  = tid >> 4;
    const int bc4 = (tid & 15) * 4;

    const float* wnbase = nullptr;
    if (job == 1 && aAct && lm < 490) {
        int o = lm / 49, p = lm % 49;
        wnbase = (o < 2 ? wnote + (size_t)o * 25088
                        : wreg  + (size_t)(o - 2) * 25088) + p;
    }

    auto loadA = [&](int k0, float va[4]) {
        if (!aAct) { va[0] = va[1] = va[2] = va[3] = 0.0f; return; }
        if (job == 1) {
            if (wnbase) {
#pragma unroll
                for (int j = 0; j < 4; j++) va[j] = wnbase[(size_t)(k0 + lk4 + j) * 49];
            } else { va[0] = va[1] = va[2] = va[3] = 0.0f; }
        } else {
            if (lm < M) {
                float4 t = *(const float4*)&A[(size_t)lm * 512 + k0 + lk4];
                va[0] = t.x; va[1] = t.y; va[2] = t.z; va[3] = t.w;
            } else { va[0] = va[1] = va[2] = va[3] = 0.0f; }
        }
    };

    // prologue: tile k0=0 -> buffer 0
    {
        float va[4];
        loadA(0, va);
        float4 bv = *(const float4*)&B[(size_t)br * 512 + n0 + bc4];
        if (aAct) {
#pragma unroll
            for (int j = 0; j < 4; j++) As[0][lk4 + j][lmr] = va[j];
        }
        *(float4*)&Bs[0][br][bc4] = bv;
    }
    __syncthreads();

    for (int k0 = 0; k0 < 512; k0 += 16) {
        const int buf = (k0 >> 4) & 1;
        const bool has = (k0 + 16 < 512);
        float va2[4]; float4 bv2;
        if (has) {
            loadA(k0 + 16, va2);
            bv2 = *(const float4*)&B[(size_t)(k0 + 16 + br) * 512 + n0 + bc4];
        }

#pragma unroll
        for (int k = 0; k < 16; k++) {
            float af[RM], bf[4];
#pragma unroll
            for (int i = 0; i < RM; i++) af[i] = As[buf][k][ty * RM + i];
            float4 b = *(const float4*)&Bs[buf][k][tx * 4];
            bf[0] = b.x; bf[1] = b.y; bf[2] = b.z; bf[3] = b.w;
#pragma unroll
            for (int i = 0; i < RM; i++)
#pragma unroll
                for (int j = 0; j < 4; j++)
                    acc[i][j] = fmaf(af[i], bf[j], acc[i][j]);
        }

        if (has) {
            if (aAct) {
#pragma unroll
                for (int j = 0; j < 4; j++) As[buf ^ 1][lk4 + j][lmr] = va2[j];
            }
            *(float4*)&Bs[buf ^ 1][br][bc4] = bv2;
        }
        __syncthreads();
    }

    if (job == 2) {
        // transposed store: D0T[c2][m]
#pragma unroll
        for (int i = 0; i < RM; i++) {
            int m = m0 + ty * RM + i;
            if (m < M) {
#pragma unroll
                for (int j = 0; j < 4; j++)
                    g_D0T[(size_t)(n0 + tx * 4 + j) * 512 + m] = acc[i][j];
            }
        }
    } else {
        float* C = (job == 0) ? g_W21 : g_Amat;
#pragma unroll
        for (int i = 0; i < RM; i++) {
            int m = m0 + ty * RM + i;
            if (m < M)
                *(float4*)&C[(size_t)m * 512 + n0 + tx * 4] =
                    make_float4(acc[i][0], acc[i][1], acc[i][2], acc[i][3]);
        }
    }
}

// ---------------- bias1: b2eff = w2 @ b1 + b2 ----------------
__global__ void bias1_kernel(const float* __restrict__ w2,
                             const float* __restrict__ b1,
                             const float* __restrict__ b2)
{
    const int warp = threadIdx.x >> 5, lane = threadIdx.x & 31;
    const int r = blockIdx.x * 8 + warp;   // 64 blocks x 8 warps = 512 rows
    float acc = 0.0f;
    for (int c = lane; c < 512; c += 32)
        acc += w2[(size_t)r * 512 + c] * b1[c];
#pragma unroll
    for (int off = 16; off; off >>= 1)
        acc += __shfl_xor_sync(0xffffffffu, acc, off);
    if (lane == 0) g_b2eff[r] = acc + b2[r];
}

// ---------------- bias2: const[o] ----------------
// const[o] = bhead[o] + sum_{c,p} wn[o,c,p]*b3[c] + sum_{p,c2} Amat[(o,p),c2]*b2eff[c2]
__global__ void bias2_kernel(const float* __restrict__ b3,
                             const float* __restrict__ wnote,
                             const float* __restrict__ wreg,
                             const float* __restrict__ bnote,
                             const float* __restrict__ breg)
{
    const int o = blockIdx.x;              // 10 blocks
    const int tid = threadIdx.x;           // 256
    const float* wn = (o < 2) ? wnote + (size_t)o * 25088
                              : wreg  + (size_t)(o - 2) * 25088;
    float acc = 0.0f;
    // term1: 25088 = 512*49, coalesced over wn
    for (int idx = tid; idx < 25088; idx += 256)
        acc += wn[idx] * b3[idx / 49];
    // term2: 25088 = 49*512, coalesced over Amat rows
    const float* ab = g_Amat + (size_t)o * 49 * 512;
    for (int idx = tid; idx < 25088; idx += 256)
        acc += ab[idx] * g_b2eff[idx & 511];

    __shared__ float red[256];
    red[tid] = acc;
    __syncthreads();
    for (int s = 128; s > 0; s >>= 1) {
        if (tid < s) red[tid] += red[tid + s];
        __syncthreads();
    }
    if (tid == 0)
        g_const[o] = ((o < 2) ? bnote[o] : breg[o - 2]) + red[0];
}

// ---------------- fold bilinear R: D0T -> scalar planes g_Df ----------------
// g_Df[o][c0*196+q] = sum_{py,px} wy(py,qy)*wx(px,qx) * D0T[c0][o*49+py*7+px]
// Footprint per source pixel q along one axis: <=2 sample contributors.
__global__ __launch_bounds__(256) void fold_kernel()
{
    __shared__ float srow[490];
    __shared__ float wT[14][2];
    __shared__ int   pT[14][2];
    __shared__ int   cT[14];

    const int c0 = blockIdx.x;
    for (int i = threadIdx.x; i < 490; i += 256)
        srow[i] = g_D0T[(size_t)c0 * 512 + i];

    if (threadIdx.x < 14) {
        const int qi = threadIdx.x;
        // sampling grid (exact fp32 sequence as reference; box [0,0,13,13])
        const float sh   = 13.0f / 7.0f;
        const float ny0  = (sh * 0.5f - 0.5f) / 13.0f;
        const float nh   = sh * 6.0f / 13.0f;
        const float step = (nh * 13.0f) / 6.0f;
        const float base = ny0 * 13.0f;
        int cnt = 0;
#pragma unroll
        for (int p = 0; p < 7; p++) {
            float yv  = base + (float)p * step;
            float y0f = floorf(yv);
            float fy  = yv - y0f;
            int   y0c = max(0, min((int)y0f, 13));
            int   y1c = min(y0c + 1, 13);
            float w   = (qi == y0c) ? (1.0f - fy) : ((qi == y1c) ? fy : 0.0f);
            if (w != 0.0f && cnt < 2) { pT[qi][cnt] = p; wT[qi][cnt] = w; cnt++; }
        }
        cT[qi] = cnt;
    }
    __syncthreads();

    for (int t = threadIdx.x; t < 1960; t += 256) {
        const int o = t / 196;
        const int q = t % 196;
        const int qy = q / 14, qx = q % 14;
        const int cy = cT[qy], cx = cT[qx];
        float v = 0.0f;
        for (int iy = 0; iy < cy; iy++) {
            const float wy = wT[qy][iy];
            const int   py = pT[qy][iy];
            for (int ix = 0; ix < cx; ix++)
                v = fmaf(wy * wT[qx][ix], srow[o * 49 + py * 7 + pT[qx][ix]], v);
        }
        g_Df[(size_t)o * KTOT + (size_t)c0 * 196 + q] = v;
    }
}

// ---------------- main streaming pass (scalar FFMA, smem D subtiles) ----------
// grid (CHUNKS=28, 16); block 256 = 8 warps; warp handles 4 consecutive n.
// Per subtile: block stages 896k x 10o of D in smem (35KB), then each warp
// streams proj (float4 per n) and accumulates 4n x 4k x 10o scalar FFMAs.
__global__ __launch_bounds__(256) void main_kernel(const float* __restrict__ proj)
{
    __shared__ float sD[10 * KS];          // 35840 B

    const int tid  = threadIdx.x;
    const int warp = tid >> 5, lane = tid & 31;
    const int n0 = (blockIdx.y * 8 + warp) * 4;
    const size_t kbase = (size_t)blockIdx.x * KCH;
    const float* p0 = proj + (size_t)n0 * KTOT + kbase;

    float acc[4][10];
#pragma unroll
    for (int i = 0; i < 4; i++)
#pragma unroll
        for (int o = 0; o < 10; o++) acc[i][o] = 0.0f;

    for (int st = 0; st < KCH / KS; st++) {
        __syncthreads();                   // previous subtile compute done
        // stage D subtile: 10 planes x KS floats = 2240 float4s
        for (int idx = tid; idx < 10 * KS / 4; idx += 256) {
            const int o  = idx / (KS / 4);
            const int k4 = idx - o * (KS / 4);
            *(float4*)&sD[o * KS + k4 * 4] =
                *(const float4*)(g_Df + (size_t)o * KTOT + kbase + st * KS + k4 * 4);
        }
        __syncthreads();

        const float* pp = p0 + (size_t)st * KS;
#pragma unroll 1
        for (int it = 0; it < KS / 128; it++) {
            const int koff = it * 128 + lane * 4;
            float4 pv[4];
#pragma unroll
            for (int i = 0; i < 4; i++)
                pv[i] = *(const float4*)(pp + (size_t)i * KTOT + koff);
#pragma unroll
            for (int o = 0; o < 10; o++) {
                float4 d = *(const float4*)&sD[o * KS + koff];
#pragma unroll
                for (int i = 0; i < 4; i++) {
                    acc[i][o] = fmaf(pv[i].x, d.x, acc[i][o]);
                    acc[i][o] = fmaf(pv[i].y, d.y, acc[i][o]);
                    acc[i][o] = fmaf(pv[i].z, d.z, acc[i][o]);
                    acc[i][o] = fmaf(pv[i].w, d.w, acc[i][o]);
                }
            }
        }
    }

    // warp butterfly reduce
#pragma unroll
    for (int i = 0; i < 4; i++)
#pragma unroll
        for (int o = 0; o < 10; o++) {
            float v = acc[i][o];
#pragma unroll
            for (int off = 16; off; off >>= 1)
                v += __shfl_xor_sync(0xffffffffu, v, off);
            acc[i][o] = v;
        }

    if (lane == 0) {
#pragma unroll
        for (int i = 0; i < 4; i++) {
            float* dst = g_part + ((size_t)blockIdx.x * 512 + (n0 + i)) * 10;
#pragma unroll
            for (int o = 0; o < 10; o++) dst[o] = acc[i][o];
        }
    }
}

// ---------------- final reduce over k-chunks + bias ----------------
__global__ void final_kernel(float* __restrict__ out)
{
    const int i = blockIdx.x * 256 + threadIdx.x;  // 5120 outputs
    if (i >= 5120) return;
    int n, o;
    if (i < 1024) { n = i >> 1; o = i & 1; }
    else          { int j = i - 1024; n = j >> 3; o = 2 + (j & 7); }
    float s = g_const[o];
#pragma unroll
    for (int c = 0; c < CHUNKS; c++)
        s += g_part[((size_t)c * 512 + n) * 10 + o];
    out[i] = s;
}

// ---------------- launch ----------------
extern "C" void kernel_launch(void* const* d_in, const int* in_sizes, int n_in,
                              void* d_out, int out_size)
{
    const float* project = (const float*)d_in[0];
    const float* w1    = (const float*)d_in[1];
    const float* b1    = (const float*)d_in[2];
    const float* w2    = (const float*)d_in[3];
    const float* b2    = (const float*)d_in[4];
    const float* w3    = (const float*)d_in[5];
    const float* b3    = (const float*)d_in[6];
    const float* wnote = (const float*)d_in[7];
    const float* bnote = (const float*)d_in[8];
    const float* wreg  = (const float*)d_in[9];
    const float* breg  = (const float*)d_in[10];
    float* out = (float*)d_out;

    // b2eff (inputs only)
    bias1_kernel<<<64, 256>>>(w2, b1, b2);
    // W21 = w2@w1 and Amat = wn (x)_c w3 : one launch, 128 blocks (1 wave)
    gemm_kernel<64><<<dim3(8, 8, 2), 256>>>(w1, w2, w3, wnote, wreg, 0);
    // D0T = (Amat @ W21)^T : 32x64 tiles -> 128 blocks (1 wave)
    gemm_kernel<32><<<dim3(8, 16, 1), 256>>>(w1, w2, w3, wnote, wreg, 2);
    // const[o] (needs Amat)
    bias2_kernel<<<10, 256>>>(b3, wnote, wreg, bnote, breg);
    // fold bilinear R into scalar planes
    fold_kernel<<<512, 256>>>();
    // streaming contraction
    main_kernel<<<dim3(CHUNKS, 16), 256>>>(project);
    // reduce partials + bias
    final_kernel<<<20, 256>>>(out);
}